// round 13
// baseline (speedup 1.0000x reference)
#include <cuda_runtime.h>
#include <cuda_bf16.h>

// CompactBilinearPooling: count-sketch into O=16384 buckets + circular conv
// via FFT. Persistent CTAs: grid = B/2, each CTA does rows b and b+128;
// twiddle table built once; row-1 zeroing + input prefetch overlapped with
// row-0's inverse epilogue. 512 threads, 32 elements/thread; radix-32,
// radix-32, radix-16 DIF groups with immediate-rotation twiddles.
// Pointwise product via difference of squares: P = (Z^2 - conj(W^2))/(4i)
// (threads publish squared spectra; partner step is 4 instr/element).
// 1/(4N) folded into the pointwise constants.

#define N_FFT    16384
#define LOG2N    14
#define D_IN     4096
#define NTHREADS 512
#define TW_N     4096
#define Z_SLOTS  17408
#define ROWS     2

__device__ __forceinline__ int slotof(int i) { return i + 2 * (i >> 5); }

// packed fp32x2 add/sub (sm_103a)
__device__ __forceinline__ float2 cadd(float2 a, float2 b) {
    float2 r;
    asm("{\n\t.reg .b64 ra, rb, rc;\n\t"
        "mov.b64 ra, {%2,%3};\n\t"
        "mov.b64 rb, {%4,%5};\n\t"
        "add.rn.f32x2 rc, ra, rb;\n\t"
        "mov.b64 {%0,%1}, rc;\n\t}"
        : "=f"(r.x), "=f"(r.y)
        : "f"(a.x), "f"(a.y), "f"(b.x), "f"(b.y));
    return r;
}
__device__ __forceinline__ float2 csub(float2 a, float2 b) {
    float2 r;
    asm("{\n\t.reg .b64 ra, rb, rc;\n\t"
        "mov.b64 ra, {%2,%3};\n\t"
        "mov.b64 rb, {%4,%5};\n\t"
        "sub.rn.f32x2 rc, ra, rb;\n\t"
        "mov.b64 {%0,%1}, rc;\n\t}"
        : "=f"(r.x), "=f"(r.y)
        : "f"(a.x), "f"(a.y), "f"(b.x), "f"(b.y));
    return r;
}
__device__ __forceinline__ float2 cmul(float2 a, float2 b) {
    return make_float2(fmaf(a.x, b.x, -a.y * b.y),
                       fmaf(a.x, b.y,  a.y * b.x));
}
__device__ __forceinline__ float2 cconj(float2 a) {
    return make_float2(a.x, -a.y);
}
// complex square: (x^2 - y^2, 2xy)
__device__ __forceinline__ float2 csq(float2 a) {
    return make_float2(fmaf(a.x, a.x, -a.y * a.y), 2.0f * a.x * a.y);
}
// w * (c + i s) with c, s immediates
__device__ __forceinline__ float2 twmul(float2 w, float c, float s) {
    return make_float2(fmaf(w.x, c, -w.y * s), fmaf(w.x, s, w.y * c));
}

// twiddle fetch for indices in [0, 8192): table holds k < 4096;
// w^(4096+r) = -i * w^r = (s, -c)
__device__ __forceinline__ float2 twr2(const float2* tw, int idx) {
    float2 t = tw[idx & (TW_N - 1)];
    return (idx & TW_N) ? make_float2(t.y, -t.x) : t;
}

// position <-> frequency involution for digit pattern [2,2,1,2,2,1,2,2]
__device__ __forceinline__ int rho(int j) {
    unsigned b = __brev((unsigned)j) >> (32 - LOG2N);
    return (int)(((b & 0x14A5u) << 1) | ((b >> 1) & 0x14A5u) | (b & 0x0210u));
}

// radix-4 DIF with all three twiddles given
__device__ __forceinline__ void dif_w(float2& a0, float2& a1, float2& a2,
                                      float2& a3, float2 w1, float2 w2,
                                      float2 w3) {
    float2 t0 = cadd(a0, a2), t1 = csub(a0, a2);
    float2 t2 = cadd(a1, a3), t3 = csub(a1, a3);
    float2 y0 = cadd(t0, t2);
    float2 y2 = csub(t0, t2);
    float2 y1 = make_float2(t1.x + t3.y, t1.y - t3.x);   // t1 - i*t3
    float2 y3 = make_float2(t1.x - t3.y, t1.y + t3.x);   // t1 + i*t3
    a0 = y0;
    a1 = cmul(y1, w1);
    a2 = cmul(y2, w2);
    a3 = cmul(y3, w3);
}
// radix-4 DIF, w == 1
__device__ __forceinline__ void dif_nt(float2& a0, float2& a1, float2& a2,
                                       float2& a3) {
    float2 t0 = cadd(a0, a2), t1 = csub(a0, a2);
    float2 t2 = cadd(a1, a3), t3 = csub(a1, a3);
    a0 = cadd(t0, t2);
    a2 = csub(t0, t2);
    a1 = make_float2(t1.x + t3.y, t1.y - t3.x);
    a3 = make_float2(t1.x - t3.y, t1.y + t3.x);
}
// radix-4 DIT with all three conj twiddles given
__device__ __forceinline__ void dit_w(float2& a0, float2& a1, float2& a2,
                                      float2& a3, float2 w1c, float2 w2c,
                                      float2 w3c) {
    float2 t1 = cmul(a1, w1c), t2 = cmul(a2, w2c), t3 = cmul(a3, w3c);
    float2 e0 = cadd(a0, t2), e1 = csub(a0, t2);
    float2 e2 = cadd(t1, t3), e3 = csub(t1, t3);
    a0 = cadd(e0, e2);
    a1 = make_float2(e1.x - e3.y, e1.y + e3.x);          // e1 + i*e3
    a2 = csub(e0, e2);
    a3 = make_float2(e1.x + e3.y, e1.y - e3.x);          // e1 - i*e3
}
// radix-4 DIT, w == 1
__device__ __forceinline__ void dit_nt(float2& a0, float2& a1, float2& a2,
                                       float2& a3) {
    float2 e0 = cadd(a0, a2), e1 = csub(a0, a2);
    float2 e2 = cadd(a1, a3), e3 = csub(a1, a3);
    a0 = cadd(e0, e2);
    a1 = make_float2(e1.x - e3.y, e1.y + e3.x);
    a2 = csub(e0, e2);
    a3 = make_float2(e1.x + e3.y, e1.y - e3.x);
}

// radix-2 DIF / DIT
__device__ __forceinline__ void dif2(float2& a, float2& b, float2 w) {
    float2 s = cadd(a, b), d = csub(a, b);
    a = s;
    b = cmul(d, w);
}
__device__ __forceinline__ void dit2(float2& a, float2& b, float2 wc) {
    float2 t = cmul(b, wc);
    b = csub(a, t);
    a = cadd(a, t);
}

// twiddle constants
#define C16A 0.92387953251128674f
#define S16A 0.38268343236508978f
#define RS2  0.70710678118654752f
#define C32A 0.98078528040323044f
#define S32A 0.19509032201612827f
#define C32B 0.83146961230254524f
#define S32B 0.55557023301960218f

// 32-point DIF on v[0..31]; base twiddles w1=tw[n], w2=tw[4n], wr=tw[16n].
__device__ __forceinline__ void fwd32(float2* v, float2 w1, float2 w2,
                                      float2 wr) {
    float2 w1s = cmul(w1, w1), w1t = cmul(w1s, w1);
    dif_w(v[0], v[8], v[16], v[24], w1, w1s, w1t);
    dif_w(v[1], v[9], v[17], v[25],
          twmul(w1, C32A, -S32A), twmul(w1s, C16A, -S16A),
          twmul(w1t, C32B, -S32B));
    dif_w(v[2], v[10], v[18], v[26],
          twmul(w1, C16A, -S16A), twmul(w1s, RS2, -RS2),
          twmul(w1t, S16A, -C16A));
    dif_w(v[3], v[11], v[19], v[27],
          twmul(w1, C32B, -S32B), twmul(w1s, S16A, -C16A),
          twmul(w1t, -S32A, -C32A));
    dif_w(v[4], v[12], v[20], v[28],
          twmul(w1, RS2, -RS2), twmul(w1s, 0.0f, -1.0f),
          twmul(w1t, -RS2, -RS2));
    dif_w(v[5], v[13], v[21], v[29],
          twmul(w1, S32B, -C32B), twmul(w1s, -S16A, -C16A),
          twmul(w1t, -C32A, -S32A));
    dif_w(v[6], v[14], v[22], v[30],
          twmul(w1, S16A, -C16A), twmul(w1s, -RS2, -RS2),
          twmul(w1t, -C16A, S16A));
    dif_w(v[7], v[15], v[23], v[31],
          twmul(w1, S32A, -C32A), twmul(w1s, -C16A, -S16A),
          twmul(w1t, -S32B, C32B));
    float2 w2s = cmul(w2, w2), w2t = cmul(w2s, w2);
    float2 w2b  = twmul(w2, RS2, -RS2);
    float2 w2bs = make_float2(w2s.y, -w2s.x);
    float2 w2bt = twmul(w2t, -RS2, -RS2);
    #pragma unroll
    for (int mb = 0; mb < 32; mb += 8) {
        dif_w(v[mb],     v[mb + 2], v[mb + 4], v[mb + 6], w2, w2s, w2t);
        dif_w(v[mb + 1], v[mb + 3], v[mb + 5], v[mb + 7], w2b, w2bs, w2bt);
    }
    #pragma unroll
    for (int m = 0; m < 32; m += 2) dif2(v[m], v[m + 1], wr);
}
__device__ __forceinline__ void inv32(float2* v, float2 w1c, float2 w2c,
                                      float2 wrc) {
    #pragma unroll
    for (int m = 0; m < 32; m += 2) dit2(v[m], v[m + 1], wrc);
    float2 w2cs = cmul(w2c, w2c), w2ct = cmul(w2cs, w2c);
    float2 w2bc  = twmul(w2c, RS2, RS2);
    float2 w2bcs = make_float2(-w2cs.y, w2cs.x);
    float2 w2bct = twmul(w2ct, -RS2, RS2);
    #pragma unroll
    for (int mb = 0; mb < 32; mb += 8) {
        dit_w(v[mb],     v[mb + 2], v[mb + 4], v[mb + 6], w2c, w2cs, w2ct);
        dit_w(v[mb + 1], v[mb + 3], v[mb + 5], v[mb + 7], w2bc, w2bcs, w2bct);
    }
    float2 w1cs = cmul(w1c, w1c), w1ct = cmul(w1cs, w1c);
    dit_w(v[0], v[8], v[16], v[24], w1c, w1cs, w1ct);
    dit_w(v[1], v[9], v[17], v[25],
          twmul(w1c, C32A, S32A), twmul(w1cs, C16A, S16A),
          twmul(w1ct, C32B, S32B));
    dit_w(v[2], v[10], v[18], v[26],
          twmul(w1c, C16A, S16A), twmul(w1cs, RS2, RS2),
          twmul(w1ct, S16A, C16A));
    dit_w(v[3], v[11], v[19], v[27],
          twmul(w1c, C32B, S32B), twmul(w1cs, S16A, C16A),
          twmul(w1ct, -S32A, C32A));
    dit_w(v[4], v[12], v[20], v[28],
          twmul(w1c, RS2, RS2), twmul(w1cs, 0.0f, 1.0f),
          twmul(w1ct, -RS2, RS2));
    dit_w(v[5], v[13], v[21], v[29],
          twmul(w1c, S32B, C32B), twmul(w1cs, -S16A, C16A),
          twmul(w1ct, -C32A, S32A));
    dit_w(v[6], v[14], v[22], v[30],
          twmul(w1c, S16A, C16A), twmul(w1cs, -RS2, RS2),
          twmul(w1ct, -C16A, -S16A));
    dit_w(v[7], v[15], v[23], v[31],
          twmul(w1c, S32A, C32A), twmul(w1cs, -C16A, S16A),
          twmul(w1ct, -S32B, -C32B));
}

// 16-point DIF/DIT on contiguous register elements, all-immediate twiddles
__device__ __forceinline__ void fwd16(float2* v) {
    dif_nt(v[0], v[4], v[8], v[12]);
    dif_w(v[1], v[5], v[9], v[13],
          make_float2( C16A, -S16A), make_float2( RS2, -RS2),
          make_float2( S16A, -C16A));
    dif_w(v[2], v[6], v[10], v[14],
          make_float2( RS2, -RS2), make_float2(0.0f, -1.0f),
          make_float2(-RS2, -RS2));
    dif_w(v[3], v[7], v[11], v[15],
          make_float2( S16A, -C16A), make_float2(-RS2, -RS2),
          make_float2(-C16A,  S16A));
    #pragma unroll
    for (int q = 0; q < 4; ++q)
        dif_nt(v[4 * q], v[4 * q + 1], v[4 * q + 2], v[4 * q + 3]);
}
__device__ __forceinline__ void inv16(float2* v) {
    #pragma unroll
    for (int q = 0; q < 4; ++q)
        dit_nt(v[4 * q], v[4 * q + 1], v[4 * q + 2], v[4 * q + 3]);
    dit_nt(v[0], v[4], v[8], v[12]);
    dit_w(v[1], v[5], v[9], v[13],
          make_float2( C16A,  S16A), make_float2( RS2,  RS2),
          make_float2( S16A,  C16A));
    dit_w(v[2], v[6], v[10], v[14],
          make_float2( RS2,  RS2), make_float2(0.0f, 1.0f),
          make_float2(-RS2,  RS2));
    dit_w(v[3], v[7], v[11], v[15],
          make_float2( S16A,  C16A), make_float2(-RS2,  RS2),
          make_float2(-C16A, -S16A));
}

__global__ __launch_bounds__(NTHREADS, 1)
void cbp_fft32q_kernel(const float* __restrict__ x1,
                       const float* __restrict__ x2,
                       const int*   __restrict__ h1,
                       const float* __restrict__ s1,
                       float*       __restrict__ out)
{
    extern __shared__ float2 smem[];
    float2* z  = smem;              // padded work array
    float2* tw = smem + Z_SLOTS;    // [TW_N] exp(-i*pi*k/8192)
    float4* z4 = reinterpret_cast<float4*>(smem);

    const int tid = threadIdx.x;

    // --- prefetch row-0 inputs; h1/s1 are row-invariant (loaded once) ---
    float4 pa1[2], pa2[2], pss[2];
    int4   phh[2];
    {
        const float4* x1v = reinterpret_cast<const float4*>(
            x1 + (size_t)blockIdx.x * D_IN);
        const float4* x2v = reinterpret_cast<const float4*>(
            x2 + (size_t)blockIdx.x * D_IN);
        const int4*   h1v = reinterpret_cast<const int4*>(h1);
        const float4* s1v = reinterpret_cast<const float4*>(s1);
        #pragma unroll
        for (int it = 0; it < 2; ++it) {
            int idx = tid + it * NTHREADS;
            pa1[it] = x1v[idx];
            pa2[it] = x2v[idx];
            phh[it] = h1v[idx];
            pss[it] = s1v[idx];
        }
    }

    // --- twiddles built ONCE: 2 sincospif, rest by constant rotations ---
    {
        const float2 cA = make_float2(C16A, -S16A);
        const float2 cB = make_float2(RS2,  -RS2);
        const float2 cC = make_float2(S16A, -C16A);
        #pragma unroll
        for (int it = 0; it < 2; ++it) {
            int k = tid + it * NTHREADS;     // k < 1024
            float s, c;
            sincospif(-(float)k * (1.0f / 8192.0f), &s, &c);
            float2 w = make_float2(c, s);
            tw[k]        = w;
            tw[k + 1024] = cmul(w, cA);
            tw[k + 2048] = cmul(w, cB);
            tw[k + 3072] = cmul(w, cC);
        }
    }
    // --- zero the padded work array ---
    #pragma unroll
    for (int i = tid; i < Z_SLOTS / 2; i += NTHREADS)
        z4[i] = make_float4(0.0f, 0.0f, 0.0f, 0.0f);
    __syncthreads();

    #pragma unroll 1
    for (int r = 0; r < ROWS; ++r) {
        const int b = blockIdx.x + r * gridDim.x;

        // --- count-sketch scatter from prefetched registers ---
        #pragma unroll
        for (int it = 0; it < 2; ++it) {
            float4 a1 = pa1[it];
            float4 a2 = pa2[it];
            int4   hh = phh[it];
            float4 ss = pss[it];
            int s0 = slotof(hh.x), s1i = slotof(hh.y);
            int s2 = slotof(hh.z), s3 = slotof(hh.w);
            atomicAdd(&z[s0].x,  ss.x * a1.x);
            atomicAdd(&z[s0].y,  ss.x * a2.x);
            atomicAdd(&z[s1i].x, ss.y * a1.y);
            atomicAdd(&z[s1i].y, ss.y * a2.y);
            atomicAdd(&z[s2].x,  ss.z * a1.z);
            atomicAdd(&z[s2].y,  ss.z * a2.z);
            atomicAdd(&z[s3].x,  ss.w * a1.w);
            atomicAdd(&z[s3].y,  ss.w * a2.w);
        }
        __syncthreads();

        float2 v[32];

        // ============ forward group A: 5 bits, stride 512 ============
        {
            const int np = tid;
            #pragma unroll
            for (int m = 0; m < 32; ++m) v[m] = z[slotof(np + m * 512)];
            fwd32(v, tw[np], tw[np << 2], twr2(tw, np << 4));
            #pragma unroll
            for (int m = 0; m < 32; ++m) z[slotof(np + m * 512)] = v[m];
        }
        __syncthreads();

        // ========= forward group B: 5 bits, stride 16 in 512-blocks =======
        {
            const int lane = tid & 15;
            const int base = (tid >> 4) * 512 + lane;
            #pragma unroll
            for (int m = 0; m < 32; ++m) v[m] = z[slotof(base + m * 16)];
            fwd32(v, tw[lane << 5], tw[lane << 7], twr2(tw, lane << 9));
            #pragma unroll
            for (int m = 0; m < 32; ++m) z[slotof(base + m * 16)] = v[m];
        }
        __syncwarp();   // exchange with group C is warp-local

        // ==== fused: group C -> squared publish -> pointwise -> group C' ====
        {
            const int f4base = 17 * tid;     // float4 index of own block
            #pragma unroll
            for (int j = 0; j < 16; ++j) {
                float4 q = z4[f4base + j];
                v[2 * j]     = make_float2(q.x, q.y);
                v[2 * j + 1] = make_float2(q.z, q.w);
            }
            fwd16(v);
            fwd16(v + 16);
            // square own spectrum: S = Z^2, publish S
            #pragma unroll
            for (int m = 0; m < 32; ++m) v[m] = csq(v[m]);
            #pragma unroll
            for (int j = 0; j < 16; ++j)
                z4[f4base + j] = make_float4(v[2 * j].x, v[2 * j].y,
                                             v[2 * j + 1].x, v[2 * j + 1].y);
            __syncthreads();

            // P = (S - conj(Sp)) * (-i/4N):
            // P.x = (S.y + Sp.y)*C4, P.y = (Sp.x - S.x)*C4
            const float C4 = 0.25f / (float)N_FFT;   // exact power of 2
            if (tid != 0) {
                const int khi = rho(32 * tid);
                const int pb  = rho(512 - khi);        // 32-aligned block
                const int pf4 = 17 * (pb >> 5);
                #pragma unroll
                for (int jj = 0; jj < 16; ++jj) {
                    float4 pq = z4[pf4 + 15 - jj];
                    float2 S0 = v[2 * jj];       // pairs high half (z,w)
                    float2 S1 = v[2 * jj + 1];   // pairs low half  (x,y)
                    v[2 * jj]     = make_float2((S0.y + pq.w) * C4,
                                                (pq.z - S0.x) * C4);
                    v[2 * jj + 1] = make_float2((S1.y + pq.y) * C4,
                                                (pq.x - S1.x) * C4);
                }
            } else {
                // block 0 partners itself; general per-element path
                #pragma unroll
                for (int m = 0; m < 32; ++m) {
                    int k  = rho(m);
                    int nk = (N_FFT - k) & (N_FFT - 1);
                    int pj = rho(nk);
                    float2 S  = v[m];
                    float2 Sp = z[slotof(pj)];
                    v[m] = make_float2((S.y + Sp.y) * C4,
                                       (Sp.x - S.x) * C4);
                }
            }
            __syncthreads();   // partner reads done before overwriting z

            inv16(v);
            inv16(v + 16);
            #pragma unroll
            for (int j = 0; j < 16; ++j)
                z4[f4base + j] = make_float4(v[2 * j].x, v[2 * j].y,
                                             v[2 * j + 1].x, v[2 * j + 1].y);
        }
        __syncwarp();   // exchange with group B' is warp-local

        // ============ inverse group B' ============
        {
            const int lane = tid & 15;
            const int base = (tid >> 4) * 512 + lane;
            #pragma unroll
            for (int m = 0; m < 32; ++m) v[m] = z[slotof(base + m * 16)];
            inv32(v, cconj(tw[lane << 5]), cconj(tw[lane << 7]),
                  cconj(twr2(tw, lane << 9)));
            #pragma unroll
            for (int m = 0; m < 32; ++m) z[slotof(base + m * 16)] = v[m];
        }
        __syncthreads();

        // ====== inverse group A' + epilogue (+ overlapped next-row prep) ====
        {
            const int np = tid;
            #pragma unroll
            for (int m = 0; m < 32; ++m) v[m] = z[slotof(np + m * 512)];
            __syncthreads();   // all A' reads of z complete -> z reusable

            if (r + 1 < ROWS) {
                // prefetch next row's x1/x2 (h1/s1 persist in registers)
                const int bn = blockIdx.x + (r + 1) * gridDim.x;
                const float4* x1v = reinterpret_cast<const float4*>(
                    x1 + (size_t)bn * D_IN);
                const float4* x2v = reinterpret_cast<const float4*>(
                    x2 + (size_t)bn * D_IN);
                #pragma unroll
                for (int it = 0; it < 2; ++it) {
                    int idx = tid + it * NTHREADS;
                    pa1[it] = x1v[idx];
                    pa2[it] = x2v[idx];
                }
                // zero z for the next row (overlaps with inv32 below)
                #pragma unroll
                for (int i = tid; i < Z_SLOTS / 2; i += NTHREADS)
                    z4[i] = make_float4(0.0f, 0.0f, 0.0f, 0.0f);
            }

            inv32(v, cconj(tw[np]), cconj(tw[np << 2]),
                  cconj(twr2(tw, np << 4)));
            float* outr = out + (size_t)b * N_FFT;
            #pragma unroll
            for (int m = 0; m < 32; ++m)
                outr[np + m * 512] = v[m].x;    // 1/(4N) already folded in
        }
        if (r + 1 < ROWS)
            __syncthreads();   // zero stores drained before next scatter
    }
}

extern "C" void kernel_launch(void* const* d_in, const int* in_sizes, int n_in,
                              void* d_out, int out_size)
{
    const float* x1 = (const float*)d_in[0];
    const float* x2 = (const float*)d_in[1];
    const int*   h1 = (const int*)  d_in[2];
    const float* s1 = (const float*)d_in[3];
    float*       out = (float*)d_out;

    const int smem_bytes = (Z_SLOTS + TW_N) * (int)sizeof(float2);  // 172032
    cudaFuncSetAttribute(cbp_fft32q_kernel,
                         cudaFuncAttributeMaxDynamicSharedMemorySize,
                         smem_bytes);

    const int batch = out_size / N_FFT;       // 256
    const int grid  = batch / ROWS;           // 128
    cbp_fft32q_kernel<<<grid, NTHREADS, smem_bytes>>>(x1, x2, h1, s1, out);
}

// round 14
// speedup vs baseline: 1.1150x; 1.1150x over previous
#include <cuda_runtime.h>
#include <cuda_bf16.h>

// CompactBilinearPooling: count-sketch into O=16384 buckets + circular conv
// via FFT. Persistent CTAs: grid = B/2, each CTA does rows b and b+128;
// twiddle table built once. 512 threads, 32 elements/thread; radix-32,
// radix-32, radix-16 DIF groups with immediate-rotation twiddles (3 smem
// twiddle loads per strided group). Pointwise product via difference of
// squares: P = (Z^2 - conj(W^2)) * (-i/4N) — threads publish squared
// spectra; the partner step is 4 instructions/element. NO cross-row
// overlap (it spilled registers in R13). 1/(4N) folded in.

#define N_FFT    16384
#define LOG2N    14
#define D_IN     4096
#define NTHREADS 512
#define TW_N     4096
#define Z_SLOTS  17408
#define ROWS     2

__device__ __forceinline__ int slotof(int i) { return i + 2 * (i >> 5); }

// packed fp32x2 add/sub (sm_103a)
__device__ __forceinline__ float2 cadd(float2 a, float2 b) {
    float2 r;
    asm("{\n\t.reg .b64 ra, rb, rc;\n\t"
        "mov.b64 ra, {%2,%3};\n\t"
        "mov.b64 rb, {%4,%5};\n\t"
        "add.rn.f32x2 rc, ra, rb;\n\t"
        "mov.b64 {%0,%1}, rc;\n\t}"
        : "=f"(r.x), "=f"(r.y)
        : "f"(a.x), "f"(a.y), "f"(b.x), "f"(b.y));
    return r;
}
__device__ __forceinline__ float2 csub(float2 a, float2 b) {
    float2 r;
    asm("{\n\t.reg .b64 ra, rb, rc;\n\t"
        "mov.b64 ra, {%2,%3};\n\t"
        "mov.b64 rb, {%4,%5};\n\t"
        "sub.rn.f32x2 rc, ra, rb;\n\t"
        "mov.b64 {%0,%1}, rc;\n\t}"
        : "=f"(r.x), "=f"(r.y)
        : "f"(a.x), "f"(a.y), "f"(b.x), "f"(b.y));
    return r;
}
__device__ __forceinline__ float2 cmul(float2 a, float2 b) {
    return make_float2(fmaf(a.x, b.x, -a.y * b.y),
                       fmaf(a.x, b.y,  a.y * b.x));
}
__device__ __forceinline__ float2 cconj(float2 a) {
    return make_float2(a.x, -a.y);
}
// complex square: (x^2 - y^2, 2xy)
__device__ __forceinline__ float2 csq(float2 a) {
    return make_float2(fmaf(a.x, a.x, -a.y * a.y), 2.0f * a.x * a.y);
}
// w * (c + i s) with c, s immediates
__device__ __forceinline__ float2 twmul(float2 w, float c, float s) {
    return make_float2(fmaf(w.x, c, -w.y * s), fmaf(w.x, s, w.y * c));
}

// twiddle fetch for indices in [0, 8192): table holds k < 4096;
// w^(4096+r) = -i * w^r = (s, -c)
__device__ __forceinline__ float2 twr2(const float2* tw, int idx) {
    float2 t = tw[idx & (TW_N - 1)];
    return (idx & TW_N) ? make_float2(t.y, -t.x) : t;
}

// position <-> frequency involution for digit pattern [2,2,1,2,2,1,2,2]
__device__ __forceinline__ int rho(int j) {
    unsigned b = __brev((unsigned)j) >> (32 - LOG2N);
    return (int)(((b & 0x14A5u) << 1) | ((b >> 1) & 0x14A5u) | (b & 0x0210u));
}

// radix-4 DIF with all three twiddles given
__device__ __forceinline__ void dif_w(float2& a0, float2& a1, float2& a2,
                                      float2& a3, float2 w1, float2 w2,
                                      float2 w3) {
    float2 t0 = cadd(a0, a2), t1 = csub(a0, a2);
    float2 t2 = cadd(a1, a3), t3 = csub(a1, a3);
    float2 y0 = cadd(t0, t2);
    float2 y2 = csub(t0, t2);
    float2 y1 = make_float2(t1.x + t3.y, t1.y - t3.x);   // t1 - i*t3
    float2 y3 = make_float2(t1.x - t3.y, t1.y + t3.x);   // t1 + i*t3
    a0 = y0;
    a1 = cmul(y1, w1);
    a2 = cmul(y2, w2);
    a3 = cmul(y3, w3);
}
// radix-4 DIF, w == 1
__device__ __forceinline__ void dif_nt(float2& a0, float2& a1, float2& a2,
                                       float2& a3) {
    float2 t0 = cadd(a0, a2), t1 = csub(a0, a2);
    float2 t2 = cadd(a1, a3), t3 = csub(a1, a3);
    a0 = cadd(t0, t2);
    a2 = csub(t0, t2);
    a1 = make_float2(t1.x + t3.y, t1.y - t3.x);
    a3 = make_float2(t1.x - t3.y, t1.y + t3.x);
}
// radix-4 DIT with all three conj twiddles given
__device__ __forceinline__ void dit_w(float2& a0, float2& a1, float2& a2,
                                      float2& a3, float2 w1c, float2 w2c,
                                      float2 w3c) {
    float2 t1 = cmul(a1, w1c), t2 = cmul(a2, w2c), t3 = cmul(a3, w3c);
    float2 e0 = cadd(a0, t2), e1 = csub(a0, t2);
    float2 e2 = cadd(t1, t3), e3 = csub(t1, t3);
    a0 = cadd(e0, e2);
    a1 = make_float2(e1.x - e3.y, e1.y + e3.x);          // e1 + i*e3
    a2 = csub(e0, e2);
    a3 = make_float2(e1.x + e3.y, e1.y - e3.x);          // e1 - i*e3
}
// radix-4 DIT, w == 1
__device__ __forceinline__ void dit_nt(float2& a0, float2& a1, float2& a2,
                                       float2& a3) {
    float2 e0 = cadd(a0, a2), e1 = csub(a0, a2);
    float2 e2 = cadd(a1, a3), e3 = csub(a1, a3);
    a0 = cadd(e0, e2);
    a1 = make_float2(e1.x - e3.y, e1.y + e3.x);
    a2 = csub(e0, e2);
    a3 = make_float2(e1.x + e3.y, e1.y - e3.x);
}

// radix-2 DIF / DIT
__device__ __forceinline__ void dif2(float2& a, float2& b, float2 w) {
    float2 s = cadd(a, b), d = csub(a, b);
    a = s;
    b = cmul(d, w);
}
__device__ __forceinline__ void dit2(float2& a, float2& b, float2 wc) {
    float2 t = cmul(b, wc);
    b = csub(a, t);
    a = cadd(a, t);
}

// twiddle constants
#define C16A 0.92387953251128674f
#define S16A 0.38268343236508978f
#define RS2  0.70710678118654752f
#define C32A 0.98078528040323044f
#define S32A 0.19509032201612827f
#define C32B 0.83146961230254524f
#define S32B 0.55557023301960218f

// 32-point DIF on v[0..31]; base twiddles w1=tw[n], w2=tw[4n], wr=tw[16n].
__device__ __forceinline__ void fwd32(float2* v, float2 w1, float2 w2,
                                      float2 wr) {
    float2 w1s = cmul(w1, w1), w1t = cmul(w1s, w1);
    dif_w(v[0], v[8], v[16], v[24], w1, w1s, w1t);
    dif_w(v[1], v[9], v[17], v[25],
          twmul(w1, C32A, -S32A), twmul(w1s, C16A, -S16A),
          twmul(w1t, C32B, -S32B));
    dif_w(v[2], v[10], v[18], v[26],
          twmul(w1, C16A, -S16A), twmul(w1s, RS2, -RS2),
          twmul(w1t, S16A, -C16A));
    dif_w(v[3], v[11], v[19], v[27],
          twmul(w1, C32B, -S32B), twmul(w1s, S16A, -C16A),
          twmul(w1t, -S32A, -C32A));
    dif_w(v[4], v[12], v[20], v[28],
          twmul(w1, RS2, -RS2), twmul(w1s, 0.0f, -1.0f),
          twmul(w1t, -RS2, -RS2));
    dif_w(v[5], v[13], v[21], v[29],
          twmul(w1, S32B, -C32B), twmul(w1s, -S16A, -C16A),
          twmul(w1t, -C32A, -S32A));
    dif_w(v[6], v[14], v[22], v[30],
          twmul(w1, S16A, -C16A), twmul(w1s, -RS2, -RS2),
          twmul(w1t, -C16A, S16A));
    dif_w(v[7], v[15], v[23], v[31],
          twmul(w1, S32A, -C32A), twmul(w1s, -C16A, -S16A),
          twmul(w1t, -S32B, C32B));
    float2 w2s = cmul(w2, w2), w2t = cmul(w2s, w2);
    float2 w2b  = twmul(w2, RS2, -RS2);
    float2 w2bs = make_float2(w2s.y, -w2s.x);
    float2 w2bt = twmul(w2t, -RS2, -RS2);
    #pragma unroll
    for (int mb = 0; mb < 32; mb += 8) {
        dif_w(v[mb],     v[mb + 2], v[mb + 4], v[mb + 6], w2, w2s, w2t);
        dif_w(v[mb + 1], v[mb + 3], v[mb + 5], v[mb + 7], w2b, w2bs, w2bt);
    }
    #pragma unroll
    for (int m = 0; m < 32; m += 2) dif2(v[m], v[m + 1], wr);
}
__device__ __forceinline__ void inv32(float2* v, float2 w1c, float2 w2c,
                                      float2 wrc) {
    #pragma unroll
    for (int m = 0; m < 32; m += 2) dit2(v[m], v[m + 1], wrc);
    float2 w2cs = cmul(w2c, w2c), w2ct = cmul(w2cs, w2c);
    float2 w2bc  = twmul(w2c, RS2, RS2);
    float2 w2bcs = make_float2(-w2cs.y, w2cs.x);
    float2 w2bct = twmul(w2ct, -RS2, RS2);
    #pragma unroll
    for (int mb = 0; mb < 32; mb += 8) {
        dit_w(v[mb],     v[mb + 2], v[mb + 4], v[mb + 6], w2c, w2cs, w2ct);
        dit_w(v[mb + 1], v[mb + 3], v[mb + 5], v[mb + 7], w2bc, w2bcs, w2bct);
    }
    float2 w1cs = cmul(w1c, w1c), w1ct = cmul(w1cs, w1c);
    dit_w(v[0], v[8], v[16], v[24], w1c, w1cs, w1ct);
    dit_w(v[1], v[9], v[17], v[25],
          twmul(w1c, C32A, S32A), twmul(w1cs, C16A, S16A),
          twmul(w1ct, C32B, S32B));
    dit_w(v[2], v[10], v[18], v[26],
          twmul(w1c, C16A, S16A), twmul(w1cs, RS2, RS2),
          twmul(w1ct, S16A, C16A));
    dit_w(v[3], v[11], v[19], v[27],
          twmul(w1c, C32B, S32B), twmul(w1cs, S16A, C16A),
          twmul(w1ct, -S32A, C32A));
    dit_w(v[4], v[12], v[20], v[28],
          twmul(w1c, RS2, RS2), twmul(w1cs, 0.0f, 1.0f),
          twmul(w1ct, -RS2, RS2));
    dit_w(v[5], v[13], v[21], v[29],
          twmul(w1c, S32B, C32B), twmul(w1cs, -S16A, C16A),
          twmul(w1ct, -C32A, S32A));
    dit_w(v[6], v[14], v[22], v[30],
          twmul(w1c, S16A, C16A), twmul(w1cs, -RS2, RS2),
          twmul(w1ct, -C16A, -S16A));
    dit_w(v[7], v[15], v[23], v[31],
          twmul(w1c, S32A, C32A), twmul(w1cs, -C16A, S16A),
          twmul(w1ct, -S32B, -C32B));
}

// 16-point DIF/DIT on contiguous register elements, all-immediate twiddles
__device__ __forceinline__ void fwd16(float2* v) {
    dif_nt(v[0], v[4], v[8], v[12]);
    dif_w(v[1], v[5], v[9], v[13],
          make_float2( C16A, -S16A), make_float2( RS2, -RS2),
          make_float2( S16A, -C16A));
    dif_w(v[2], v[6], v[10], v[14],
          make_float2( RS2, -RS2), make_float2(0.0f, -1.0f),
          make_float2(-RS2, -RS2));
    dif_w(v[3], v[7], v[11], v[15],
          make_float2( S16A, -C16A), make_float2(-RS2, -RS2),
          make_float2(-C16A,  S16A));
    #pragma unroll
    for (int q = 0; q < 4; ++q)
        dif_nt(v[4 * q], v[4 * q + 1], v[4 * q + 2], v[4 * q + 3]);
}
__device__ __forceinline__ void inv16(float2* v) {
    #pragma unroll
    for (int q = 0; q < 4; ++q)
        dit_nt(v[4 * q], v[4 * q + 1], v[4 * q + 2], v[4 * q + 3]);
    dit_nt(v[0], v[4], v[8], v[12]);
    dit_w(v[1], v[5], v[9], v[13],
          make_float2( C16A,  S16A), make_float2( RS2,  RS2),
          make_float2( S16A,  C16A));
    dit_w(v[2], v[6], v[10], v[14],
          make_float2( RS2,  RS2), make_float2(0.0f, 1.0f),
          make_float2(-RS2,  RS2));
    dit_w(v[3], v[7], v[11], v[15],
          make_float2( S16A,  C16A), make_float2(-RS2,  RS2),
          make_float2(-C16A, -S16A));
}

__global__ __launch_bounds__(NTHREADS, 1)
void cbp_fft32r_kernel(const float* __restrict__ x1,
                       const float* __restrict__ x2,
                       const int*   __restrict__ h1,
                       const float* __restrict__ s1,
                       float*       __restrict__ out)
{
    extern __shared__ float2 smem[];
    float2* z  = smem;              // padded work array
    float2* tw = smem + Z_SLOTS;    // [TW_N] exp(-i*pi*k/8192)
    float4* z4 = reinterpret_cast<float4*>(smem);

    const int tid = threadIdx.x;

    // --- twiddles built ONCE: 2 sincospif, rest by constant rotations ---
    {
        const float2 cA = make_float2(C16A, -S16A);
        const float2 cB = make_float2(RS2,  -RS2);
        const float2 cC = make_float2(S16A, -C16A);
        #pragma unroll
        for (int it = 0; it < 2; ++it) {
            int k = tid + it * NTHREADS;     // k < 1024
            float s, c;
            sincospif(-(float)k * (1.0f / 8192.0f), &s, &c);
            float2 w = make_float2(c, s);
            tw[k]        = w;
            tw[k + 1024] = cmul(w, cA);
            tw[k + 2048] = cmul(w, cB);
            tw[k + 3072] = cmul(w, cC);
        }
    }

    #pragma unroll 1
    for (int r = 0; r < ROWS; ++r) {
        const int b = blockIdx.x + r * gridDim.x;

        // barrier: row r-1 epilogue z-reads (and twiddle writes on r=0)
        // must complete before zeroing
        __syncthreads();

        // --- prefetch inputs (hidden behind zeroing) ---
        float4 pa1[2], pa2[2], pss[2];
        int4   phh[2];
        {
            const float4* x1v = reinterpret_cast<const float4*>(x1 + (size_t)b * D_IN);
            const float4* x2v = reinterpret_cast<const float4*>(x2 + (size_t)b * D_IN);
            const int4*   h1v = reinterpret_cast<const int4*>(h1);
            const float4* s1v = reinterpret_cast<const float4*>(s1);
            #pragma unroll
            for (int it = 0; it < 2; ++it) {
                int idx = tid + it * NTHREADS;
                pa1[it] = x1v[idx];
                pa2[it] = x2v[idx];
                phh[it] = h1v[idx];
                pss[it] = s1v[idx];
            }
        }

        // --- zero the padded work array (float4 stores) ---
        #pragma unroll
        for (int i = tid; i < Z_SLOTS / 2; i += NTHREADS)
            z4[i] = make_float4(0.0f, 0.0f, 0.0f, 0.0f);
        __syncthreads();

        // --- count-sketch scatter from prefetched registers ---
        #pragma unroll
        for (int it = 0; it < 2; ++it) {
            float4 a1 = pa1[it];
            float4 a2 = pa2[it];
            int4   hh = phh[it];
            float4 ss = pss[it];
            int s0 = slotof(hh.x), s1i = slotof(hh.y);
            int s2 = slotof(hh.z), s3 = slotof(hh.w);
            atomicAdd(&z[s0].x,  ss.x * a1.x);
            atomicAdd(&z[s0].y,  ss.x * a2.x);
            atomicAdd(&z[s1i].x, ss.y * a1.y);
            atomicAdd(&z[s1i].y, ss.y * a2.y);
            atomicAdd(&z[s2].x,  ss.z * a1.z);
            atomicAdd(&z[s2].y,  ss.z * a2.z);
            atomicAdd(&z[s3].x,  ss.w * a1.w);
            atomicAdd(&z[s3].y,  ss.w * a2.w);
        }
        __syncthreads();

        float2 v[32];

        // ============ forward group A: 5 bits, stride 512 ============
        {
            const int np = tid;
            #pragma unroll
            for (int m = 0; m < 32; ++m) v[m] = z[slotof(np + m * 512)];
            fwd32(v, tw[np], tw[np << 2], twr2(tw, np << 4));
            #pragma unroll
            for (int m = 0; m < 32; ++m) z[slotof(np + m * 512)] = v[m];
        }
        __syncthreads();

        // ========= forward group B: 5 bits, stride 16 in 512-blocks =======
        {
            const int lane = tid & 15;
            const int base = (tid >> 4) * 512 + lane;
            #pragma unroll
            for (int m = 0; m < 32; ++m) v[m] = z[slotof(base + m * 16)];
            fwd32(v, tw[lane << 5], tw[lane << 7], twr2(tw, lane << 9));
            #pragma unroll
            for (int m = 0; m < 32; ++m) z[slotof(base + m * 16)] = v[m];
        }
        __syncwarp();   // exchange with group C is warp-local

        // ==== fused: group C -> squared publish -> pointwise -> group C' ====
        {
            const int f4base = 17 * tid;     // float4 index of own block
            #pragma unroll
            for (int j = 0; j < 16; ++j) {
                float4 q = z4[f4base + j];
                v[2 * j]     = make_float2(q.x, q.y);
                v[2 * j + 1] = make_float2(q.z, q.w);
            }
            fwd16(v);
            fwd16(v + 16);
            // square own spectrum: S = Z^2, publish S
            #pragma unroll
            for (int m = 0; m < 32; ++m) v[m] = csq(v[m]);
            #pragma unroll
            for (int j = 0; j < 16; ++j)
                z4[f4base + j] = make_float4(v[2 * j].x, v[2 * j].y,
                                             v[2 * j + 1].x, v[2 * j + 1].y);
            __syncthreads();

            // P = (S - conj(Sp)) * (-i/4N):
            // P.x = (S.y + Sp.y)*C4, P.y = (Sp.x - S.x)*C4
            const float C4 = 0.25f / (float)N_FFT;   // exact power of 2
            if (tid != 0) {
                const int khi = rho(32 * tid);
                const int pb  = rho(512 - khi);        // 32-aligned block
                const int pf4 = 17 * (pb >> 5);
                #pragma unroll
                for (int jj = 0; jj < 16; ++jj) {
                    float4 pq = z4[pf4 + 15 - jj];
                    float2 S0 = v[2 * jj];       // pairs high half (z,w)
                    float2 S1 = v[2 * jj + 1];   // pairs low half  (x,y)
                    v[2 * jj]     = make_float2((S0.y + pq.w) * C4,
                                                (pq.z - S0.x) * C4);
                    v[2 * jj + 1] = make_float2((S1.y + pq.y) * C4,
                                                (pq.x - S1.x) * C4);
                }
            } else {
                // block 0 partners itself; general per-element path
                #pragma unroll
                for (int m = 0; m < 32; ++m) {
                    int k  = rho(m);
                    int nk = (N_FFT - k) & (N_FFT - 1);
                    int pj = rho(nk);
                    float2 S  = v[m];
                    float2 Sp = z[slotof(pj)];
                    v[m] = make_float2((S.y + Sp.y) * C4,
                                       (Sp.x - S.x) * C4);
                }
            }
            __syncthreads();   // partner reads done before overwriting z

            inv16(v);
            inv16(v + 16);
            #pragma unroll
            for (int j = 0; j < 16; ++j)
                z4[f4base + j] = make_float4(v[2 * j].x, v[2 * j].y,
                                             v[2 * j + 1].x, v[2 * j + 1].y);
        }
        __syncwarp();   // exchange with group B' is warp-local

        // ============ inverse group B' ============
        {
            const int lane = tid & 15;
            const int base = (tid >> 4) * 512 + lane;
            #pragma unroll
            for (int m = 0; m < 32; ++m) v[m] = z[slotof(base + m * 16)];
            inv32(v, cconj(tw[lane << 5]), cconj(tw[lane << 7]),
                  cconj(twr2(tw, lane << 9)));
            #pragma unroll
            for (int m = 0; m < 32; ++m) z[slotof(base + m * 16)] = v[m];
        }
        __syncthreads();

        // ============ inverse group A' + fused gmem epilogue ============
        {
            const int np = tid;
            #pragma unroll
            for (int m = 0; m < 32; ++m) v[m] = z[slotof(np + m * 512)];
            inv32(v, cconj(tw[np]), cconj(tw[np << 2]),
                  cconj(twr2(tw, np << 4)));
            float* outr = out + (size_t)b * N_FFT;
            #pragma unroll
            for (int m = 0; m < 32; ++m)
                outr[np + m * 512] = v[m].x;    // 1/(4N) already folded in
        }
    }
}

extern "C" void kernel_launch(void* const* d_in, const int* in_sizes, int n_in,
                              void* d_out, int out_size)
{
    const float* x1 = (const float*)d_in[0];
    const float* x2 = (const float*)d_in[1];
    const int*   h1 = (const int*)  d_in[2];
    const float* s1 = (const float*)d_in[3];
    float*       out = (float*)d_out;

    const int smem_bytes = (Z_SLOTS + TW_N) * (int)sizeof(float2);  // 172032
    cudaFuncSetAttribute(cbp_fft32r_kernel,
                         cudaFuncAttributeMaxDynamicSharedMemorySize,
                         smem_bytes);

    const int batch = out_size / N_FFT;       // 256
    const int grid  = batch / ROWS;           // 128
    cbp_fft32r_kernel<<<grid, NTHREADS, smem_bytes>>>(x1, x2, h1, s1, out);
}

// round 15
// speedup vs baseline: 1.1704x; 1.0497x over previous
#include <cuda_runtime.h>
#include <cuda_bf16.h>

// CompactBilinearPooling: count-sketch into O=16384 buckets + circular conv
// via FFT. Persistent CTAs: grid = B/2, each CTA does rows b and b+128;
// twiddle table built once. 512 threads, 32 elements/thread; radix-32,
// radix-32, radix-16 DIF groups with immediate-rotation twiddles.
// Pointwise product via difference of squares: P = (Z^2 - conj(W^2))*(-i/4N).
// Threads publish squared spectra S, then RELOAD own S from smem after the
// barrier (v[] dies across the barrier -> no register spills; R14's version
// held v live across it and spilled). 1/(4N) folded in.

#define N_FFT    16384
#define LOG2N    14
#define D_IN     4096
#define NTHREADS 512
#define TW_N     4096
#define Z_SLOTS  17408
#define ROWS     2

__device__ __forceinline__ int slotof(int i) { return i + 2 * (i >> 5); }

// packed fp32x2 add/sub (sm_103a)
__device__ __forceinline__ float2 cadd(float2 a, float2 b) {
    float2 r;
    asm("{\n\t.reg .b64 ra, rb, rc;\n\t"
        "mov.b64 ra, {%2,%3};\n\t"
        "mov.b64 rb, {%4,%5};\n\t"
        "add.rn.f32x2 rc, ra, rb;\n\t"
        "mov.b64 {%0,%1}, rc;\n\t}"
        : "=f"(r.x), "=f"(r.y)
        : "f"(a.x), "f"(a.y), "f"(b.x), "f"(b.y));
    return r;
}
__device__ __forceinline__ float2 csub(float2 a, float2 b) {
    float2 r;
    asm("{\n\t.reg .b64 ra, rb, rc;\n\t"
        "mov.b64 ra, {%2,%3};\n\t"
        "mov.b64 rb, {%4,%5};\n\t"
        "sub.rn.f32x2 rc, ra, rb;\n\t"
        "mov.b64 {%0,%1}, rc;\n\t}"
        : "=f"(r.x), "=f"(r.y)
        : "f"(a.x), "f"(a.y), "f"(b.x), "f"(b.y));
    return r;
}
__device__ __forceinline__ float2 cmul(float2 a, float2 b) {
    return make_float2(fmaf(a.x, b.x, -a.y * b.y),
                       fmaf(a.x, b.y,  a.y * b.x));
}
__device__ __forceinline__ float2 cconj(float2 a) {
    return make_float2(a.x, -a.y);
}
// complex square: (x^2 - y^2, 2xy)
__device__ __forceinline__ float2 csq(float2 a) {
    return make_float2(fmaf(a.x, a.x, -a.y * a.y), 2.0f * a.x * a.y);
}
// w * (c + i s) with c, s immediates
__device__ __forceinline__ float2 twmul(float2 w, float c, float s) {
    return make_float2(fmaf(w.x, c, -w.y * s), fmaf(w.x, s, w.y * c));
}

// twiddle fetch for indices in [0, 8192): table holds k < 4096;
// w^(4096+r) = -i * w^r = (s, -c)
__device__ __forceinline__ float2 twr2(const float2* tw, int idx) {
    float2 t = tw[idx & (TW_N - 1)];
    return (idx & TW_N) ? make_float2(t.y, -t.x) : t;
}

// position <-> frequency involution for digit pattern [2,2,1,2,2,1,2,2]
__device__ __forceinline__ int rho(int j) {
    unsigned b = __brev((unsigned)j) >> (32 - LOG2N);
    return (int)(((b & 0x14A5u) << 1) | ((b >> 1) & 0x14A5u) | (b & 0x0210u));
}

// radix-4 DIF with all three twiddles given
__device__ __forceinline__ void dif_w(float2& a0, float2& a1, float2& a2,
                                      float2& a3, float2 w1, float2 w2,
                                      float2 w3) {
    float2 t0 = cadd(a0, a2), t1 = csub(a0, a2);
    float2 t2 = cadd(a1, a3), t3 = csub(a1, a3);
    float2 y0 = cadd(t0, t2);
    float2 y2 = csub(t0, t2);
    float2 y1 = make_float2(t1.x + t3.y, t1.y - t3.x);   // t1 - i*t3
    float2 y3 = make_float2(t1.x - t3.y, t1.y + t3.x);   // t1 + i*t3
    a0 = y0;
    a1 = cmul(y1, w1);
    a2 = cmul(y2, w2);
    a3 = cmul(y3, w3);
}
// radix-4 DIF, w == 1
__device__ __forceinline__ void dif_nt(float2& a0, float2& a1, float2& a2,
                                       float2& a3) {
    float2 t0 = cadd(a0, a2), t1 = csub(a0, a2);
    float2 t2 = cadd(a1, a3), t3 = csub(a1, a3);
    a0 = cadd(t0, t2);
    a2 = csub(t0, t2);
    a1 = make_float2(t1.x + t3.y, t1.y - t3.x);
    a3 = make_float2(t1.x - t3.y, t1.y + t3.x);
}
// radix-4 DIT with all three conj twiddles given
__device__ __forceinline__ void dit_w(float2& a0, float2& a1, float2& a2,
                                      float2& a3, float2 w1c, float2 w2c,
                                      float2 w3c) {
    float2 t1 = cmul(a1, w1c), t2 = cmul(a2, w2c), t3 = cmul(a3, w3c);
    float2 e0 = cadd(a0, t2), e1 = csub(a0, t2);
    float2 e2 = cadd(t1, t3), e3 = csub(t1, t3);
    a0 = cadd(e0, e2);
    a1 = make_float2(e1.x - e3.y, e1.y + e3.x);          // e1 + i*e3
    a2 = csub(e0, e2);
    a3 = make_float2(e1.x + e3.y, e1.y - e3.x);          // e1 - i*e3
}
// radix-4 DIT, w == 1
__device__ __forceinline__ void dit_nt(float2& a0, float2& a1, float2& a2,
                                       float2& a3) {
    float2 e0 = cadd(a0, a2), e1 = csub(a0, a2);
    float2 e2 = cadd(a1, a3), e3 = csub(a1, a3);
    a0 = cadd(e0, e2);
    a1 = make_float2(e1.x - e3.y, e1.y + e3.x);
    a2 = csub(e0, e2);
    a3 = make_float2(e1.x + e3.y, e1.y - e3.x);
}

// radix-2 DIF / DIT
__device__ __forceinline__ void dif2(float2& a, float2& b, float2 w) {
    float2 s = cadd(a, b), d = csub(a, b);
    a = s;
    b = cmul(d, w);
}
__device__ __forceinline__ void dit2(float2& a, float2& b, float2 wc) {
    float2 t = cmul(b, wc);
    b = csub(a, t);
    a = cadd(a, t);
}

// twiddle constants
#define C16A 0.92387953251128674f
#define S16A 0.38268343236508978f
#define RS2  0.70710678118654752f
#define C32A 0.98078528040323044f
#define S32A 0.19509032201612827f
#define C32B 0.83146961230254524f
#define S32B 0.55557023301960218f

// 32-point DIF on v[0..31]; base twiddles w1=tw[n], w2=tw[4n], wr=tw[16n].
__device__ __forceinline__ void fwd32(float2* v, float2 w1, float2 w2,
                                      float2 wr) {
    float2 w1s = cmul(w1, w1), w1t = cmul(w1s, w1);
    dif_w(v[0], v[8], v[16], v[24], w1, w1s, w1t);
    dif_w(v[1], v[9], v[17], v[25],
          twmul(w1, C32A, -S32A), twmul(w1s, C16A, -S16A),
          twmul(w1t, C32B, -S32B));
    dif_w(v[2], v[10], v[18], v[26],
          twmul(w1, C16A, -S16A), twmul(w1s, RS2, -RS2),
          twmul(w1t, S16A, -C16A));
    dif_w(v[3], v[11], v[19], v[27],
          twmul(w1, C32B, -S32B), twmul(w1s, S16A, -C16A),
          twmul(w1t, -S32A, -C32A));
    dif_w(v[4], v[12], v[20], v[28],
          twmul(w1, RS2, -RS2), twmul(w1s, 0.0f, -1.0f),
          twmul(w1t, -RS2, -RS2));
    dif_w(v[5], v[13], v[21], v[29],
          twmul(w1, S32B, -C32B), twmul(w1s, -S16A, -C16A),
          twmul(w1t, -C32A, -S32A));
    dif_w(v[6], v[14], v[22], v[30],
          twmul(w1, S16A, -C16A), twmul(w1s, -RS2, -RS2),
          twmul(w1t, -C16A, S16A));
    dif_w(v[7], v[15], v[23], v[31],
          twmul(w1, S32A, -C32A), twmul(w1s, -C16A, -S16A),
          twmul(w1t, -S32B, C32B));
    float2 w2s = cmul(w2, w2), w2t = cmul(w2s, w2);
    float2 w2b  = twmul(w2, RS2, -RS2);
    float2 w2bs = make_float2(w2s.y, -w2s.x);
    float2 w2bt = twmul(w2t, -RS2, -RS2);
    #pragma unroll
    for (int mb = 0; mb < 32; mb += 8) {
        dif_w(v[mb],     v[mb + 2], v[mb + 4], v[mb + 6], w2, w2s, w2t);
        dif_w(v[mb + 1], v[mb + 3], v[mb + 5], v[mb + 7], w2b, w2bs, w2bt);
    }
    #pragma unroll
    for (int m = 0; m < 32; m += 2) dif2(v[m], v[m + 1], wr);
}
__device__ __forceinline__ void inv32(float2* v, float2 w1c, float2 w2c,
                                      float2 wrc) {
    #pragma unroll
    for (int m = 0; m < 32; m += 2) dit2(v[m], v[m + 1], wrc);
    float2 w2cs = cmul(w2c, w2c), w2ct = cmul(w2cs, w2c);
    float2 w2bc  = twmul(w2c, RS2, RS2);
    float2 w2bcs = make_float2(-w2cs.y, w2cs.x);
    float2 w2bct = twmul(w2ct, -RS2, RS2);
    #pragma unroll
    for (int mb = 0; mb < 32; mb += 8) {
        dit_w(v[mb],     v[mb + 2], v[mb + 4], v[mb + 6], w2c, w2cs, w2ct);
        dit_w(v[mb + 1], v[mb + 3], v[mb + 5], v[mb + 7], w2bc, w2bcs, w2bct);
    }
    float2 w1cs = cmul(w1c, w1c), w1ct = cmul(w1cs, w1c);
    dit_w(v[0], v[8], v[16], v[24], w1c, w1cs, w1ct);
    dit_w(v[1], v[9], v[17], v[25],
          twmul(w1c, C32A, S32A), twmul(w1cs, C16A, S16A),
          twmul(w1ct, C32B, S32B));
    dit_w(v[2], v[10], v[18], v[26],
          twmul(w1c, C16A, S16A), twmul(w1cs, RS2, RS2),
          twmul(w1ct, S16A, C16A));
    dit_w(v[3], v[11], v[19], v[27],
          twmul(w1c, C32B, S32B), twmul(w1cs, S16A, C16A),
          twmul(w1ct, -S32A, C32A));
    dit_w(v[4], v[12], v[20], v[28],
          twmul(w1c, RS2, RS2), twmul(w1cs, 0.0f, 1.0f),
          twmul(w1ct, -RS2, RS2));
    dit_w(v[5], v[13], v[21], v[29],
          twmul(w1c, S32B, C32B), twmul(w1cs, -S16A, C16A),
          twmul(w1ct, -C32A, S32A));
    dit_w(v[6], v[14], v[22], v[30],
          twmul(w1c, S16A, C16A), twmul(w1cs, -RS2, RS2),
          twmul(w1ct, -C16A, -S16A));
    dit_w(v[7], v[15], v[23], v[31],
          twmul(w1c, S32A, C32A), twmul(w1cs, -C16A, S16A),
          twmul(w1ct, -S32B, -C32B));
}

// 16-point DIF/DIT on contiguous register elements, all-immediate twiddles
__device__ __forceinline__ void fwd16(float2* v) {
    dif_nt(v[0], v[4], v[8], v[12]);
    dif_w(v[1], v[5], v[9], v[13],
          make_float2( C16A, -S16A), make_float2( RS2, -RS2),
          make_float2( S16A, -C16A));
    dif_w(v[2], v[6], v[10], v[14],
          make_float2( RS2, -RS2), make_float2(0.0f, -1.0f),
          make_float2(-RS2, -RS2));
    dif_w(v[3], v[7], v[11], v[15],
          make_float2( S16A, -C16A), make_float2(-RS2, -RS2),
          make_float2(-C16A,  S16A));
    #pragma unroll
    for (int q = 0; q < 4; ++q)
        dif_nt(v[4 * q], v[4 * q + 1], v[4 * q + 2], v[4 * q + 3]);
}
__device__ __forceinline__ void inv16(float2* v) {
    #pragma unroll
    for (int q = 0; q < 4; ++q)
        dit_nt(v[4 * q], v[4 * q + 1], v[4 * q + 2], v[4 * q + 3]);
    dit_nt(v[0], v[4], v[8], v[12]);
    dit_w(v[1], v[5], v[9], v[13],
          make_float2( C16A,  S16A), make_float2( RS2,  RS2),
          make_float2( S16A,  C16A));
    dit_w(v[2], v[6], v[10], v[14],
          make_float2( RS2,  RS2), make_float2(0.0f, 1.0f),
          make_float2(-RS2,  RS2));
    dit_w(v[3], v[7], v[11], v[15],
          make_float2( S16A,  C16A), make_float2(-RS2,  RS2),
          make_float2(-C16A, -S16A));
}

__global__ __launch_bounds__(NTHREADS, 1)
void cbp_fft32s_kernel(const float* __restrict__ x1,
                       const float* __restrict__ x2,
                       const int*   __restrict__ h1,
                       const float* __restrict__ s1,
                       float*       __restrict__ out)
{
    extern __shared__ float2 smem[];
    float2* z  = smem;              // padded work array
    float2* tw = smem + Z_SLOTS;    // [TW_N] exp(-i*pi*k/8192)
    float4* z4 = reinterpret_cast<float4*>(smem);

    const int tid = threadIdx.x;

    // --- twiddles built ONCE: 2 sincospif, rest by constant rotations ---
    {
        const float2 cA = make_float2(C16A, -S16A);
        const float2 cB = make_float2(RS2,  -RS2);
        const float2 cC = make_float2(S16A, -C16A);
        #pragma unroll
        for (int it = 0; it < 2; ++it) {
            int k = tid + it * NTHREADS;     // k < 1024
            float s, c;
            sincospif(-(float)k * (1.0f / 8192.0f), &s, &c);
            float2 w = make_float2(c, s);
            tw[k]        = w;
            tw[k + 1024] = cmul(w, cA);
            tw[k + 2048] = cmul(w, cB);
            tw[k + 3072] = cmul(w, cC);
        }
    }

    #pragma unroll 1
    for (int r = 0; r < ROWS; ++r) {
        const int b = blockIdx.x + r * gridDim.x;

        // barrier: row r-1 epilogue z-reads (and twiddle writes on r=0)
        // must complete before zeroing
        __syncthreads();

        // --- prefetch inputs (hidden behind zeroing) ---
        float4 pa1[2], pa2[2], pss[2];
        int4   phh[2];
        {
            const float4* x1v = reinterpret_cast<const float4*>(x1 + (size_t)b * D_IN);
            const float4* x2v = reinterpret_cast<const float4*>(x2 + (size_t)b * D_IN);
            const int4*   h1v = reinterpret_cast<const int4*>(h1);
            const float4* s1v = reinterpret_cast<const float4*>(s1);
            #pragma unroll
            for (int it = 0; it < 2; ++it) {
                int idx = tid + it * NTHREADS;
                pa1[it] = x1v[idx];
                pa2[it] = x2v[idx];
                phh[it] = h1v[idx];
                pss[it] = s1v[idx];
            }
        }

        // --- zero the padded work array (float4 stores) ---
        #pragma unroll
        for (int i = tid; i < Z_SLOTS / 2; i += NTHREADS)
            z4[i] = make_float4(0.0f, 0.0f, 0.0f, 0.0f);
        __syncthreads();

        // --- count-sketch scatter from prefetched registers ---
        #pragma unroll
        for (int it = 0; it < 2; ++it) {
            float4 a1 = pa1[it];
            float4 a2 = pa2[it];
            int4   hh = phh[it];
            float4 ss = pss[it];
            int s0 = slotof(hh.x), s1i = slotof(hh.y);
            int s2 = slotof(hh.z), s3 = slotof(hh.w);
            atomicAdd(&z[s0].x,  ss.x * a1.x);
            atomicAdd(&z[s0].y,  ss.x * a2.x);
            atomicAdd(&z[s1i].x, ss.y * a1.y);
            atomicAdd(&z[s1i].y, ss.y * a2.y);
            atomicAdd(&z[s2].x,  ss.z * a1.z);
            atomicAdd(&z[s2].y,  ss.z * a2.z);
            atomicAdd(&z[s3].x,  ss.w * a1.w);
            atomicAdd(&z[s3].y,  ss.w * a2.w);
        }
        __syncthreads();

        float2 v[32];

        // ============ forward group A: 5 bits, stride 512 ============
        {
            const int np = tid;
            #pragma unroll
            for (int m = 0; m < 32; ++m) v[m] = z[slotof(np + m * 512)];
            fwd32(v, tw[np], tw[np << 2], twr2(tw, np << 4));
            #pragma unroll
            for (int m = 0; m < 32; ++m) z[slotof(np + m * 512)] = v[m];
        }
        __syncthreads();

        // ========= forward group B: 5 bits, stride 16 in 512-blocks =======
        {
            const int lane = tid & 15;
            const int base = (tid >> 4) * 512 + lane;
            #pragma unroll
            for (int m = 0; m < 32; ++m) v[m] = z[slotof(base + m * 16)];
            fwd32(v, tw[lane << 5], tw[lane << 7], twr2(tw, lane << 9));
            #pragma unroll
            for (int m = 0; m < 32; ++m) z[slotof(base + m * 16)] = v[m];
        }
        __syncwarp();   // exchange with group C is warp-local

        // ==== fused: group C -> squared publish -> (v dies) -> pointwise
        //      from smem reloads -> group C' ====
        {
            const int f4base = 17 * tid;     // float4 index of own block
            #pragma unroll
            for (int j = 0; j < 16; ++j) {
                float4 q = z4[f4base + j];
                v[2 * j]     = make_float2(q.x, q.y);
                v[2 * j + 1] = make_float2(q.z, q.w);
            }
            fwd16(v);
            fwd16(v + 16);
            // square own spectrum: S = Z^2, publish S; v dead after this
            #pragma unroll
            for (int j = 0; j < 16; ++j) {
                float2 s0 = csq(v[2 * j]);
                float2 s1v_ = csq(v[2 * j + 1]);
                z4[f4base + j] = make_float4(s0.x, s0.y, s1v_.x, s1v_.y);
            }
            __syncthreads();

            // P = (S - conj(Sp)) * (-i/4N):
            // P.x = (S.y + Sp.y)*C4, P.y = (Sp.x - S.x)*C4
            // Reload own S (conflict-free float4) + partner S.
            const float C4 = 0.25f / (float)N_FFT;   // exact power of 2
            if (tid != 0) {
                const int khi = rho(32 * tid);
                const int pb  = rho(512 - khi);        // 32-aligned block
                const int pf4 = 17 * (pb >> 5);
                #pragma unroll
                for (int jj = 0; jj < 16; ++jj) {
                    float4 sq = z4[f4base + jj];       // own S pair
                    float4 pq = z4[pf4 + 15 - jj];     // partner S pair
                    // elem 2jj: S=(sq.x,sq.y) pairs Sp=(pq.z,pq.w)
                    v[2 * jj]     = make_float2((sq.y + pq.w) * C4,
                                                (pq.z - sq.x) * C4);
                    // elem 2jj+1: S=(sq.z,sq.w) pairs Sp=(pq.x,pq.y)
                    v[2 * jj + 1] = make_float2((sq.w + pq.y) * C4,
                                                (pq.x - sq.z) * C4);
                }
            } else {
                // block 0 partners itself; general per-element path
                #pragma unroll
                for (int m = 0; m < 32; ++m) {
                    int k  = rho(m);
                    int nk = (N_FFT - k) & (N_FFT - 1);
                    int pj = rho(nk);
                    float2 S  = z[slotof(m)];
                    float2 Sp = z[slotof(pj)];
                    v[m] = make_float2((S.y + Sp.y) * C4,
                                       (Sp.x - S.x) * C4);
                }
            }
            __syncthreads();   // partner reads done before overwriting z

            inv16(v);
            inv16(v + 16);
            #pragma unroll
            for (int j = 0; j < 16; ++j)
                z4[f4base + j] = make_float4(v[2 * j].x, v[2 * j].y,
                                             v[2 * j + 1].x, v[2 * j + 1].y);
        }
        __syncwarp();   // exchange with group B' is warp-local

        // ============ inverse group B' ============
        {
            const int lane = tid & 15;
            const int base = (tid >> 4) * 512 + lane;
            #pragma unroll
            for (int m = 0; m < 32; ++m) v[m] = z[slotof(base + m * 16)];
            inv32(v, cconj(tw[lane << 5]), cconj(tw[lane << 7]),
                  cconj(twr2(tw, lane << 9)));
            #pragma unroll
            for (int m = 0; m < 32; ++m) z[slotof(base + m * 16)] = v[m];
        }
        __syncthreads();

        // ============ inverse group A' + fused gmem epilogue ============
        {
            const int np = tid;
            #pragma unroll
            for (int m = 0; m < 32; ++m) v[m] = z[slotof(np + m * 512)];
            inv32(v, cconj(tw[np]), cconj(tw[np << 2]),
                  cconj(twr2(tw, np << 4)));
            float* outr = out + (size_t)b * N_FFT;
            #pragma unroll
            for (int m = 0; m < 32; ++m)
                outr[np + m * 512] = v[m].x;    // 1/(4N) already folded in
        }
    }
}

extern "C" void kernel_launch(void* const* d_in, const int* in_sizes, int n_in,
                              void* d_out, int out_size)
{
    const float* x1 = (const float*)d_in[0];
    const float* x2 = (const float*)d_in[1];
    const int*   h1 = (const int*)  d_in[2];
    const float* s1 = (const float*)d_in[3];
    float*       out = (float*)d_out;

    const int smem_bytes = (Z_SLOTS + TW_N) * (int)sizeof(float2);  // 172032
    cudaFuncSetAttribute(cbp_fft32s_kernel,
                         cudaFuncAttributeMaxDynamicSharedMemorySize,
                         smem_bytes);

    const int batch = out_size / N_FFT;       // 256
    const int grid  = batch / ROWS;           // 128
    cbp_fft32s_kernel<<<grid, NTHREADS, smem_bytes>>>(x1, x2, h1, s1, out);
}